// round 9
// baseline (speedup 1.0000x reference)
#include <cuda_runtime.h>

// GRU_83906481094863 — v8: v7 + register-resident W_hh front slice (sm_100a).
// B=512, T=1024, D=46, H=128. 128 CTAs x 256 threads, NB=4 batches/CTA.
//   gate threads (tid<128): unit u. W_hh k in [0,48) held in REGISTERS
//     (3 rows x 24 f32x2) -> 288 load-independent FFMA2/step that issue during
//     crossbar stalls; W_hh k in [48,128) from smem (k-chunk-major LDS.128).
//     Reads xp(t), fast nonlinearity, writes h'.
//   aux threads (tid 128-255): xp(t+1) = W_ih x(t+1) + b_ih with W_ih in
//     registers; prefetches x(t+2). ONE __syncthreads per step.

#define BB 512
#define TT 1024
#define DD 46
#define DP 48
#define HH 128
#define GG 384
#define NB 4
#define NCTA (BB/NB)   // 128
#define NTHR 256
#define NGATE 128
#define KREG 48                 // k-range in registers
#define NCH  ((HH - KREG) / 4)  // 20 smem k-chunks

// Shared floats: sW[NCH*GG*4=30720] | sH[2][NB][HH](1024) | sX[2][NB][DP](384)
//                | sXP[2][NB][GG](3072)
#define OFF_H  30720
#define OFF_X  31744
#define OFF_XP 32128
#define SMEM_FLOATS 35200
#define SMEM_BYTES  (SMEM_FLOATS * 4)   // 140800

__device__ __forceinline__ void fma2(unsigned long long &d,
                                     unsigned long long a,
                                     unsigned long long b) {
    asm("fma.rn.f32x2 %0, %1, %2, %0;" : "+l"(d) : "l"(a), "l"(b));
}
__device__ __forceinline__ float sum2(unsigned long long v) {
    float lo, hi;
    asm("mov.b64 {%0, %1}, %2;" : "=f"(lo), "=f"(hi) : "l"(v));
    return lo + hi;
}
__device__ __forceinline__ unsigned long long pack2(float lo, float hi) {
    unsigned long long v;
    asm("mov.b64 %0, {%1, %2};" : "=l"(v) : "f"(lo), "f"(hi));
    return v;
}
__device__ __forceinline__ float fast_sig(float x) {
    float e = __expf(-x);
    return __fdividef(1.f, 1.f + e);
}
__device__ __forceinline__ float fast_tanh(float x) {
    x = fminf(15.f, fmaxf(-15.f, x));
    float e = __expf(-2.f * x);
    return __fdividef(1.f - e, 1.f + e);
}

__global__ void __launch_bounds__(NTHR, 1) gru_v8(
    const float* __restrict__ history,  // [B][T][D]
    const float* __restrict__ W_ih,     // [3H][D]
    const float* __restrict__ W_hh,     // [3H][H]
    const float* __restrict__ b_ih,     // [3H]
    const float* __restrict__ b_hh,     // [3H]
    const float* __restrict__ h0,       // [H]
    float* __restrict__ out)            // [B][H]
{
    extern __shared__ float smem[];
    float* sW  = smem;                 // float4 view: (c*GG + j), c = (k>>2)-12
    float* sH  = smem + OFF_H;         // [2][NB][HH]
    float* sX  = smem + OFF_X;         // [2][NB][DP]
    float* sXP = smem + OFF_XP;        // [2][NB][GG]

    const int tid = threadIdx.x;
    const int b0  = blockIdx.x * NB;

    // ================= prologue =================
    // stage W_hh k in [48,128) k-chunk-major
    for (int idx = tid; idx < GG * (HH - KREG); idx += NTHR) {
        int j = idx / (HH - KREG), kk = idx - j * (HH - KREG);
        int k = kk + KREG;
        sW[(((k >> 2) - (KREG / 4)) * GG + j) * 4 + (k & 3)] = W_hh[j * HH + k];
    }
    // h(0)
    for (int idx = tid; idx < NB * HH; idx += NTHR)
        sH[idx] = h0[idx & 127];
    // zero x pads (both buffers)
    if (tid < 16) {
        int buf = tid >> 3, nb = (tid >> 1) & 3, d = DD + (tid & 1);
        sX[buf * (NB * DP) + nb * DP + d] = 0.f;
    }
    // x(0) -> buf0, x(1) -> buf1
    for (int idx = tid; idx < NB * DD; idx += NTHR) {
        int nb = idx / DD, d = idx - nb * DD;
        sX[nb * DP + d]           = history[(size_t)(b0 + nb) * (TT * DD) + d];
        sX[NB * DP + nb * DP + d] = history[(size_t)(b0 + nb) * (TT * DD) + DD + d];
    }

    // per-role private state
    const bool is_gate = (tid < NGATE);
    const int  u  = tid;                 // gate unit
    const int  a  = tid - NGATE;         // aux unit
    unsigned long long wreg[3][KREG / 2];   // gate: W_hh rows, k<KREG
    unsigned long long wih[3][24];          // aux: W_ih rows
    float bi[3], bh[3];
    if (is_gate) {
        #pragma unroll
        for (int g = 0; g < 3; g++) {
            const int j = u + g * HH;
            bh[g] = b_hh[j];
            #pragma unroll
            for (int p = 0; p < KREG / 2; p++)
                wreg[g][p] = pack2(W_hh[j * HH + 2 * p], W_hh[j * HH + 2 * p + 1]);
        }
    } else {
        #pragma unroll
        for (int g = 0; g < 3; g++) {
            const int j = a + g * HH;
            bi[g] = b_ih[j];
            #pragma unroll
            for (int p = 0; p < 23; p++)
                wih[g][p] = pack2(W_ih[j * DD + 2 * p], W_ih[j * DD + 2 * p + 1]);
            wih[g][23] = 0ull;
        }
    }
    const ulonglong2* wrow0 = (const ulonglong2*)sW + u;      // gate smem rows
    const ulonglong2* wrow1 = wrow0 + HH;
    const ulonglong2* wrow2 = wrow0 + 2 * HH;

    __syncthreads();

    // pre-step: aux computes xp(0) from x buf0
    if (!is_gate) {
        const float* xb = sX;
        unsigned long long ai[3][NB];
        #pragma unroll
        for (int g = 0; g < 3; g++)
            #pragma unroll
            for (int nb = 0; nb < NB; nb++) ai[g][nb] = 0ull;
        #pragma unroll
        for (int q = 0; q < 12; q++) {
            ulonglong2 xA = *(const ulonglong2*)(xb + 0 * DP + 4 * q);
            ulonglong2 xB = *(const ulonglong2*)(xb + 1 * DP + 4 * q);
            ulonglong2 xC = *(const ulonglong2*)(xb + 2 * DP + 4 * q);
            ulonglong2 xD = *(const ulonglong2*)(xb + 3 * DP + 4 * q);
            #pragma unroll
            for (int g = 0; g < 3; g++) {
                unsigned long long wa = wih[g][2 * q], wb = wih[g][2 * q + 1];
                fma2(ai[g][0], wa, xA.x); fma2(ai[g][0], wb, xA.y);
                fma2(ai[g][1], wa, xB.x); fma2(ai[g][1], wb, xB.y);
                fma2(ai[g][2], wa, xC.x); fma2(ai[g][2], wb, xC.y);
                fma2(ai[g][3], wa, xD.x); fma2(ai[g][3], wb, xD.y);
            }
        }
        #pragma unroll
        for (int g = 0; g < 3; g++)
            #pragma unroll
            for (int nb = 0; nb < NB; nb++)
                sXP[nb * GG + g * HH + a] = sum2(ai[g][nb]) + bi[g];
    }
    __syncthreads();

    // ================= main loop =================
    for (int t = 0; t < TT; t++) {
        const int cur = t & 1, nxt = cur ^ 1;

        if (is_gate) {
            const float* hb = sH + cur * (NB * HH);
            unsigned long long ah[3][NB];
            #pragma unroll
            for (int g = 0; g < 3; g++)
                #pragma unroll
                for (int nb = 0; nb < NB; nb++) ah[g][nb] = 0ull;

            // interleaved hh-dot: per iter one smem k-chunk (kc=i+12) and,
            // for i<12, one REGISTER k-chunk (kc=i) whose FMAs have no smem-W
            // dependency -> issue while W loads drain the crossbar.
            #pragma unroll
            for (int i = 0; i < NCH; i++) {
                // smem W loads first (longest dependency)
                ulonglong2 w0 = wrow0[i * GG];
                ulonglong2 w1 = wrow1[i * GG];
                ulonglong2 w2 = wrow2[i * GG];
                const int kcs = i + (KREG / 4);
                ulonglong2 sA = *(const ulonglong2*)(hb + 0 * HH + kcs * 4);
                ulonglong2 sB = *(const ulonglong2*)(hb + 1 * HH + kcs * 4);
                ulonglong2 sC = *(const ulonglong2*)(hb + 2 * HH + kcs * 4);
                ulonglong2 sD = *(const ulonglong2*)(hb + 3 * HH + kcs * 4);
                if (i < KREG / 4) {
                    // register chunk i: h broadcast only (1 wf each)
                    ulonglong2 rA = *(const ulonglong2*)(hb + 0 * HH + i * 4);
                    ulonglong2 rB = *(const ulonglong2*)(hb + 1 * HH + i * 4);
                    ulonglong2 rC = *(const ulonglong2*)(hb + 2 * HH + i * 4);
                    ulonglong2 rD = *(const ulonglong2*)(hb + 3 * HH + i * 4);
                    #pragma unroll
                    for (int g = 0; g < 3; g++) {
                        unsigned long long wa = wreg[g][2 * i], wb = wreg[g][2 * i + 1];
                        fma2(ah[g][0], wa, rA.x); fma2(ah[g][0], wb, rA.y);
                        fma2(ah[g][1], wa, rB.x); fma2(ah[g][1], wb, rB.y);
                        fma2(ah[g][2], wa, rC.x); fma2(ah[g][2], wb, rC.y);
                        fma2(ah[g][3], wa, rD.x); fma2(ah[g][3], wb, rD.y);
                    }
                }
                fma2(ah[0][0], w0.x, sA.x); fma2(ah[0][0], w0.y, sA.y);
                fma2(ah[0][1], w0.x, sB.x); fma2(ah[0][1], w0.y, sB.y);
                fma2(ah[0][2], w0.x, sC.x); fma2(ah[0][2], w0.y, sC.y);
                fma2(ah[0][3], w0.x, sD.x); fma2(ah[0][3], w0.y, sD.y);
                fma2(ah[1][0], w1.x, sA.x); fma2(ah[1][0], w1.y, sA.y);
                fma2(ah[1][1], w1.x, sB.x); fma2(ah[1][1], w1.y, sB.y);
                fma2(ah[1][2], w1.x, sC.x); fma2(ah[1][2], w1.y, sC.y);
                fma2(ah[1][3], w1.x, sD.x); fma2(ah[1][3], w1.y, sD.y);
                fma2(ah[2][0], w2.x, sA.x); fma2(ah[2][0], w2.y, sA.y);
                fma2(ah[2][1], w2.x, sB.x); fma2(ah[2][1], w2.y, sB.y);
                fma2(ah[2][2], w2.x, sC.x); fma2(ah[2][2], w2.y, sC.y);
                fma2(ah[2][3], w2.x, sD.x); fma2(ah[2][3], w2.y, sD.y);
            }

            // ---- xp(t) + nonlinearity + h update ----
            const float* xp = sXP + cur * (NB * GG);
            float* hn = sH + nxt * (NB * HH);
            #pragma unroll
            for (int nb = 0; nb < NB; nb++) {
                float x_r = xp[nb * GG + u];
                float x_z = xp[nb * GG + HH + u];
                float x_n = xp[nb * GG + 2 * HH + u];
                float g_r = sum2(ah[0][nb]) + bh[0];
                float g_z = sum2(ah[1][nb]) + bh[1];
                float g_n = sum2(ah[2][nb]) + bh[2];
                float r = fast_sig(x_r + g_r);
                float z = fast_sig(x_z + g_z);
                float n = fast_tanh(x_n + r * g_n);
                float hv = n + z * (hb[nb * HH + u] - n);
                hn[nb * HH + u] = hv;
                if (t == TT - 1)
                    out[(size_t)(b0 + nb) * HH + u] = hv;
            }
        } else {
            // ---- aux: xp(t+1) from x(t+1); prefetch x(t+2) ----
            if (t + 2 < TT) {
                #pragma unroll
                for (int r = 0; r < 2; r++) {
                    int idx = a + r * 128;
                    if (idx < NB * DD) {
                        int nb = idx / DD, d = idx - nb * DD;
                        sX[cur * (NB * DP) + nb * DP + d] =
                            history[(size_t)(b0 + nb) * (TT * DD) + (t + 2) * DD + d];
                    }
                }
            }
            if (t + 1 < TT) {
                const float* xb = sX + nxt * (NB * DP);   // x(t+1)
                unsigned long long ai[3][NB];
                #pragma unroll
                for (int g = 0; g < 3; g++)
                    #pragma unroll
                    for (int nb = 0; nb < NB; nb++) ai[g][nb] = 0ull;
                #pragma unroll
                for (int q = 0; q < 12; q++) {
                    ulonglong2 xA = *(const ulonglong2*)(xb + 0 * DP + 4 * q);
                    ulonglong2 xB = *(const ulonglong2*)(xb + 1 * DP + 4 * q);
                    ulonglong2 xC = *(const ulonglong2*)(xb + 2 * DP + 4 * q);
                    ulonglong2 xD = *(const ulonglong2*)(xb + 3 * DP + 4 * q);
                    #pragma unroll
                    for (int g = 0; g < 3; g++) {
                        unsigned long long wa = wih[g][2 * q], wb = wih[g][2 * q + 1];
                        fma2(ai[g][0], wa, xA.x); fma2(ai[g][0], wb, xA.y);
                        fma2(ai[g][1], wa, xB.x); fma2(ai[g][1], wb, xB.y);
                        fma2(ai[g][2], wa, xC.x); fma2(ai[g][2], wb, xC.y);
                        fma2(ai[g][3], wa, xD.x); fma2(ai[g][3], wb, xD.y);
                    }
                }
                float* xpn = sXP + nxt * (NB * GG);
                #pragma unroll
                for (int g = 0; g < 3; g++)
                    #pragma unroll
                    for (int nb = 0; nb < NB; nb++)
                        xpn[nb * GG + g * HH + a] = sum2(ai[g][nb]) + bi[g];
            }
        }

        __syncthreads();   // h(t+1), xp(t+1), x(t+2) all published
    }
}

extern "C" void kernel_launch(void* const* d_in, const int* in_sizes, int n_in,
                              void* d_out, int out_size) {
    const float* history = (const float*)d_in[0];
    const float* W_ih    = (const float*)d_in[1];
    const float* W_hh    = (const float*)d_in[2];
    const float* b_ih    = (const float*)d_in[3];
    const float* b_hh    = (const float*)d_in[4];
    const float* h0      = (const float*)d_in[5];
    float* out = (float*)d_out;

    cudaFuncSetAttribute(gru_v8,
                         cudaFuncAttributeMaxDynamicSharedMemorySize, SMEM_BYTES);
    gru_v8<<<NCTA, NTHR, SMEM_BYTES>>>(history, W_ih, W_hh,
                                       b_ih, b_hh, h0, out);
}

// round 10
// speedup vs baseline: 1.3295x; 1.3295x over previous
#include <cuda_runtime.h>

// GRU_83906481094863 — v9 = v2 (best, 2206us) + surgical tail cuts.
// B=512, T=1024, D=46, H=128. 128 CTAs x 192 threads, NB=4 batches/CTA.
//   threads [0,128): gate threads (4 warps, 1/SMSP). Thread u owns gate rows
//     {u, u+128, u+256}; hh-dot from smem W (k-chunk-major LDS.128, broadcast
//     h/x), ih-dot from register W_ih -- the ih FMA stream is the latency
//     filler (v7 proved removing it hurts). Nonlinearity+update in register.
//   threads [128,192): aux, prefetch x(t+1). ONE __syncthreads per step.
// Changes vs v2: MUFU sigmoid/tanh; r/z ih partials merged into hh
// accumulators (8 fewer accums/sum2); biases folded into accumulator init.

#define BB 512
#define TT 1024
#define DD 46
#define DP 48
#define HH 128
#define GG 384
#define NB 4
#define NCTA (BB/NB) // 128
#define NTHR 192
#define NGATE 128

// Shared (floats): sW[49152] W_hh k-chunk-major; sH[2][NB][HH]=1024; sX[2][NB][DP]=384
#define SMEM_FLOATS (49152 + 1024 + 384)
#define SMEM_BYTES  (SMEM_FLOATS * 4)

__device__ __forceinline__ void fma2(unsigned long long &d,
                                     unsigned long long a,
                                     unsigned long long b) {
    asm("fma.rn.f32x2 %0, %1, %2, %0;" : "+l"(d) : "l"(a), "l"(b));
}
__device__ __forceinline__ float sum2(unsigned long long v) {
    float lo, hi;
    asm("mov.b64 {%0, %1}, %2;" : "=f"(lo), "=f"(hi) : "l"(v));
    return lo + hi;
}
__device__ __forceinline__ unsigned long long pack2(float lo, float hi) {
    unsigned long long v;
    asm("mov.b64 %0, {%1, %2};" : "=l"(v) : "f"(lo), "f"(hi));
    return v;
}
// sigmoid via MUFU: 1/(1+e^-x); e=inf -> 0 (correct limit).
__device__ __forceinline__ float fast_sig(float x) {
    float e = __expf(-x);
    return __fdividef(1.f, 1.f + e);
}
// tanh via MUFU: (1-e)/(1+e), e=e^-2x, clamped so e stays finite.
__device__ __forceinline__ float fast_tanh(float x) {
    x = fminf(15.f, fmaxf(-15.f, x));
    float e = __expf(-2.f * x);
    return __fdividef(1.f - e, 1.f + e);
}

__global__ void __launch_bounds__(NTHR, 1) gru_v9(
    const float* __restrict__ history,  // [B][T][D]
    const float* __restrict__ W_ih,     // [3H][D]
    const float* __restrict__ W_hh,     // [3H][H]
    const float* __restrict__ b_ih,     // [3H]
    const float* __restrict__ b_hh,     // [3H]
    const float* __restrict__ h0,       // [H]
    float* __restrict__ out)            // [B][H]
{
    extern __shared__ float smem[];
    float* sW = smem;            // float4 view: (kc*GG + j)
    float* sH = smem + 49152;    // [2][NB][HH]
    float* sX = sH + 1024;       // [2][NB][DP]

    const int tid = threadIdx.x;
    const int b0  = blockIdx.x * NB;

    // ---- stage W_hh k-chunk-major ----
    for (int idx = tid; idx < GG * HH; idx += NTHR) {
        int j = idx >> 7, k = idx & 127;
        sW[((k >> 2) * GG + j) * 4 + (k & 3)] = W_hh[idx];
    }
    // ---- h(0) ----
    for (int idx = tid; idx < NB * HH; idx += NTHR)
        sH[idx] = h0[idx & 127];
    // ---- zero x pads ----
    if (tid < 16) {
        int buf = tid >> 3, nb = (tid >> 1) & 3, d = DD + (tid & 1);
        sX[buf * (NB * DP) + nb * DP + d] = 0.f;
    }
    // ---- x(0) ----
    for (int idx = tid; idx < NB * DD; idx += NTHR) {
        int nb = idx / DD, d = idx - nb * DD;
        sX[nb * DP + d] = history[(size_t)(b0 + nb) * (TT * DD) + d];
    }

    // ---- gate-thread private state ----
    const int u = tid;
    unsigned long long wih[3][24];
    float brz[2];       // folded r/z bias: b_ih + b_hh
    float bin2, bhn2;   // n-gate biases (must stay separate)
    if (tid < NGATE) {
        brz[0] = b_ih[u] + b_hh[u];
        brz[1] = b_ih[u + HH] + b_hh[u + HH];
        bin2 = b_ih[u + 2 * HH];
        bhn2 = b_hh[u + 2 * HH];
        #pragma unroll
        for (int g = 0; g < 3; g++) {
            const int j = u + g * HH;
            #pragma unroll
            for (int p = 0; p < 23; p++)
                wih[g][p] = pack2(W_ih[j * DD + 2 * p], W_ih[j * DD + 2 * p + 1]);
            wih[g][23] = 0ull;
        }
    }
    const ulonglong2* wrow0 = (const ulonglong2*)sW + u;      // row u
    const ulonglong2* wrow1 = wrow0 + HH;                     // row u+128
    const ulonglong2* wrow2 = wrow0 + 2 * HH;                 // row u+256

    __syncthreads();

    for (int t = 0; t < TT; t++) {
        const int cur = t & 1, nxt = cur ^ 1;

        if (tid < NGATE) {
            const float* hb = sH + cur * (NB * HH);
            const float* xb = sX + cur * (NB * DP);

            // a0/a1: full r/z preactivation (hh + ih, bias folded in)
            // a2: hh part of n (bias folded);  an: ih part of n (bias folded)
            unsigned long long a0[NB], a1[NB], a2[NB], an[NB];
            #pragma unroll
            for (int nb = 0; nb < NB; nb++) {
                a0[nb] = pack2(brz[0], 0.f);
                a1[nb] = pack2(brz[1], 0.f);
                a2[nb] = pack2(bhn2, 0.f);
                an[nb] = pack2(bin2, 0.f);
            }

            // ---- hh-dot: 32 k-chunks of 4 (smem W, broadcast h) ----
            #pragma unroll 8
            for (int kc = 0; kc < 32; kc++) {
                ulonglong2 w0 = wrow0[kc * GG];
                ulonglong2 w1 = wrow1[kc * GG];
                ulonglong2 w2 = wrow2[kc * GG];
                ulonglong2 hA = *(const ulonglong2*)(hb + 0 * HH + kc * 4);
                ulonglong2 hB = *(const ulonglong2*)(hb + 1 * HH + kc * 4);
                ulonglong2 hC = *(const ulonglong2*)(hb + 2 * HH + kc * 4);
                ulonglong2 hD = *(const ulonglong2*)(hb + 3 * HH + kc * 4);
                fma2(a0[0], w0.x, hA.x); fma2(a0[0], w0.y, hA.y);
                fma2(a0[1], w0.x, hB.x); fma2(a0[1], w0.y, hB.y);
                fma2(a0[2], w0.x, hC.x); fma2(a0[2], w0.y, hC.y);
                fma2(a0[3], w0.x, hD.x); fma2(a0[3], w0.y, hD.y);
                fma2(a1[0], w1.x, hA.x); fma2(a1[0], w1.y, hA.y);
                fma2(a1[1], w1.x, hB.x); fma2(a1[1], w1.y, hB.y);
                fma2(a1[2], w1.x, hC.x); fma2(a1[2], w1.y, hC.y);
                fma2(a1[3], w1.x, hD.x); fma2(a1[3], w1.y, hD.y);
                fma2(a2[0], w2.x, hA.x); fma2(a2[0], w2.y, hA.y);
                fma2(a2[1], w2.x, hB.x); fma2(a2[1], w2.y, hB.y);
                fma2(a2[2], w2.x, hC.x); fma2(a2[2], w2.y, hC.y);
                fma2(a2[3], w2.x, hD.x); fma2(a2[3], w2.y, hD.y);
            }
            // ---- ih-dot: r/z merge into a0/a1; n stays in an ----
            #pragma unroll
            for (int q = 0; q < 12; q++) {
                ulonglong2 xA = *(const ulonglong2*)(xb + 0 * DP + 4 * q);
                ulonglong2 xB = *(const ulonglong2*)(xb + 1 * DP + 4 * q);
                ulonglong2 xC = *(const ulonglong2*)(xb + 2 * DP + 4 * q);
                ulonglong2 xD = *(const ulonglong2*)(xb + 3 * DP + 4 * q);
                unsigned long long w0a = wih[0][2*q], w0b = wih[0][2*q+1];
                unsigned long long w1a = wih[1][2*q], w1b = wih[1][2*q+1];
                unsigned long long w2a = wih[2][2*q], w2b = wih[2][2*q+1];
                fma2(a0[0], w0a, xA.x); fma2(a0[0], w0b, xA.y);
                fma2(a0[1], w0a, xB.x); fma2(a0[1], w0b, xB.y);
                fma2(a0[2], w0a, xC.x); fma2(a0[2], w0b, xC.y);
                fma2(a0[3], w0a, xD.x); fma2(a0[3], w0b, xD.y);
                fma2(a1[0], w1a, xA.x); fma2(a1[0], w1b, xA.y);
                fma2(a1[1], w1a, xB.x); fma2(a1[1], w1b, xB.y);
                fma2(a1[2], w1a, xC.x); fma2(a1[2], w1b, xC.y);
                fma2(a1[3], w1a, xD.x); fma2(a1[3], w1b, xD.y);
                fma2(an[0], w2a, xA.x); fma2(an[0], w2b, xA.y);
                fma2(an[1], w2a, xB.x); fma2(an[1], w2b, xB.y);
                fma2(an[2], w2a, xC.x); fma2(an[2], w2b, xC.y);
                fma2(an[3], w2a, xD.x); fma2(an[3], w2b, xD.y);
            }

            // ---- nonlinearity + h update, in-register (MUFU) ----
            float* hn = sH + nxt * (NB * HH);
            #pragma unroll
            for (int nb = 0; nb < NB; nb++) {
                float r = fast_sig(sum2(a0[nb]));
                float z = fast_sig(sum2(a1[nb]));
                float n = fast_tanh(sum2(an[nb]) + r * sum2(a2[nb]));
                float hold = hb[nb * HH + u];
                float hv = n + z * (hold - n);
                hn[nb * HH + u] = hv;
                if (t == TT - 1)
                    out[(size_t)(b0 + nb) * HH + u] = hv;
            }
        } else {
            // ---- aux: prefetch x(t+1) ----
            if (t + 1 < TT) {
                const int a = tid - NGATE;   // 0..63
                #pragma unroll
                for (int r = 0; r < 3; r++) {
                    int idx = a + r * 64;
                    if (idx < NB * DD) {
                        int nb = idx / DD, d = idx - nb * DD;
                        sX[nxt * (NB * DP) + nb * DP + d] =
                            history[(size_t)(b0 + nb) * (TT * DD) + (t + 1) * DD + d];
                    }
                }
            }
        }

        __syncthreads();   // h(t+1) + x(t+1) visible
    }
}

extern "C" void kernel_launch(void* const* d_in, const int* in_sizes, int n_in,
                              void* d_out, int out_size) {
    const float* history = (const float*)d_in[0];
    const float* W_ih    = (const float*)d_in[1];
    const float* W_hh    = (const float*)d_in[2];
    const float* b_ih    = (const float*)d_in[3];
    const float* b_hh    = (const float*)d_in[4];
    const float* h0      = (const float*)d_in[5];
    float* out = (float*)d_out;

    cudaFuncSetAttribute(gru_v9,
                         cudaFuncAttributeMaxDynamicSharedMemorySize, SMEM_BYTES);
    gru_v9<<<NCTA, NTHR, SMEM_BYTES>>>(history, W_ih, W_hh,
                                       b_ih, b_hh, h0, out);
}